// round 1
// baseline (speedup 1.0000x reference)
#include <cuda_runtime.h>

// Problem constants
#define NB 2
#define LL 1024
#define EE 2048
#define HH 16
#define DD 128
#define SCALE 0.02209708691207961f   // 1/sqrt(2048)
#define NEGV  -1e20f

// Scratch (device statics; no allocations allowed)
__device__ float g_q[NB*LL*EE];
__device__ float g_k[NB*LL*EE];
__device__ float g_v[NB*LL*EE];
__device__ float g_s[NB*HH*LL*LL];   // 134 MB score matrix
__device__ float g_o[NB*LL*EE];      // attention output (n,l,h,d)
__device__ float g_cos[LL*64];
__device__ float g_sin[LL*64];

// ---------------------------------------------------------------------------
// K0: RoPE sin/cos table. freqs[l][j] = l * 10000^(-(2j)/128), j in [0,64)
// ---------------------------------------------------------------------------
__global__ void rope_tab_kernel() {
    int l = blockIdx.x;
    int j = threadIdx.x;
    float expo = (float)(2 * j) / 128.0f;
    float invf = 1.0f / powf(10000.0f, expo);
    float a = (float)l * invf;
    g_cos[l*64 + j] = cosf(a);
    g_sin[l*64 + j] = sinf(a);
}

// ---------------------------------------------------------------------------
// Shared GEMM micro-step: 256 threads (ty=tid/16, tx=tid%16), 8x8 microtile,
// As row-major [rows][AS] (k fastest), Bs k-major [16][BS] (col fastest).
// acc[ii][cc] += sum_kk As[8ty+ii][kk] * Bs[kk][8tx+cc]
// ---------------------------------------------------------------------------
template<int AS, int BS>
__device__ __forceinline__ void gemm_step(const float* As, const float* Bs,
                                          float acc[8][8], int ty, int tx) {
    #pragma unroll
    for (int kk = 0; kk < 16; kk++) {
        float a[8];
        #pragma unroll
        for (int ii = 0; ii < 8; ii++) a[ii] = As[(8*ty + ii)*AS + kk];
        float4 b0 = *reinterpret_cast<const float4*>(Bs + kk*BS + 8*tx);
        float4 b1 = *reinterpret_cast<const float4*>(Bs + kk*BS + 8*tx + 4);
        float b[8] = {b0.x, b0.y, b0.z, b0.w, b1.x, b1.y, b1.z, b1.w};
        #pragma unroll
        for (int ii = 0; ii < 8; ii++)
            #pragma unroll
            for (int cc = 0; cc < 8; cc++)
                acc[ii][cc] += a[ii] * b[cc];
    }
}

// ---------------------------------------------------------------------------
// K1: fused RoPE + per-head projection.
// Rows r = ((n*L + l)*H + h); out[r][o] = sum_d roped_x[r][d] * W[o][d]
// grid (256, 3): x = row block of 128, y = tensor (0=q rope, 1=k rope, 2=v)
// ---------------------------------------------------------------------------
__global__ __launch_bounds__(256) void proj_kernel(
    const float* __restrict__ qin, const float* __restrict__ kin,
    const float* __restrict__ vin,
    const float* __restrict__ Wq, const float* __restrict__ Wk,
    const float* __restrict__ Wv)
{
    __shared__ float As[128][17];
    __shared__ float Bs[16][132];
    int tid = threadIdx.x;
    int ty = tid >> 4, tx = tid & 15;
    int tensor = blockIdx.y;
    const float* X = (tensor == 0) ? qin : (tensor == 1) ? kin : vin;
    const float* W = (tensor == 0) ? Wq  : (tensor == 1) ? Wk  : Wv;
    float* OUT     = (tensor == 0) ? g_q : (tensor == 1) ? g_k : g_v;
    bool rope = (tensor < 2);
    int base = blockIdx.x * 128;

    float acc[8][8] = {};

    for (int k0 = 0; k0 < 128; k0 += 16) {
        // A: roped rows
        for (int i = tid; i < 128*16; i += 256) {
            int r = i >> 4, kk = i & 15;
            int rg = base + r;
            int d = k0 + kk;
            float val;
            if (rope) {
                int l = (rg >> 4) & 1023;
                int j = d & 63;
                val = X[rg*128 + d]       * g_cos[l*64 + j]
                    + X[rg*128 + 127 - d] * g_sin[l*64 + j];
            } else {
                val = X[rg*128 + d];
            }
            As[r][kk] = val;
        }
        // B: W transposed (Bs[kk][o] = W[o][k0+kk]) via coalesced float4 reads
        for (int f = tid; f < 512; f += 256) {
            int o = f >> 2, q4 = (f & 3) * 4;
            float4 w = *reinterpret_cast<const float4*>(&W[o*128 + k0 + q4]);
            Bs[q4+0][o] = w.x; Bs[q4+1][o] = w.y;
            Bs[q4+2][o] = w.z; Bs[q4+3][o] = w.w;
        }
        __syncthreads();
        gemm_step<17, 132>(&As[0][0], &Bs[0][0], acc, ty, tx);
        __syncthreads();
    }

    #pragma unroll
    for (int ii = 0; ii < 8; ii++) {
        int rg = base + 8*ty + ii;
        float4 o0 = make_float4(acc[ii][0], acc[ii][1], acc[ii][2], acc[ii][3]);
        float4 o1 = make_float4(acc[ii][4], acc[ii][5], acc[ii][6], acc[ii][7]);
        *reinterpret_cast<float4*>(&OUT[rg*128 + 8*tx])     = o0;
        *reinterpret_cast<float4*>(&OUT[rg*128 + 8*tx + 4]) = o1;
    }
}

// ---------------------------------------------------------------------------
// K2a: scores S[nh][q][k] = mask ? (q . k) * SCALE : -1e20
// grid (8, 8, 32): q block 128, k block 128, nh
// ---------------------------------------------------------------------------
__global__ __launch_bounds__(256) void score_kernel(const int* __restrict__ mask)
{
    __shared__ float As[128][17];
    __shared__ float Bs[16][132];
    int tid = threadIdx.x;
    int ty = tid >> 4, tx = tid & 15;
    int nh = blockIdx.z;
    int n = nh >> 4, h = nh & 15;
    int q0 = blockIdx.x * 128;
    int c0 = blockIdx.y * 128;

    float acc[8][8] = {};

    for (int k0 = 0; k0 < 128; k0 += 16) {
        for (int i = tid; i < 2048; i += 256) {
            int r = i >> 4, kk = i & 15;
            As[r][kk] = g_q[((n*LL + q0 + r)*HH + h)*DD + k0 + kk];
        }
        for (int i = tid; i < 2048; i += 256) {
            int c = i >> 4, kk = i & 15;
            Bs[kk][c] = g_k[((n*LL + c0 + c)*HH + h)*DD + k0 + kk];
        }
        __syncthreads();
        gemm_step<17, 132>(&As[0][0], &Bs[0][0], acc, ty, tx);
        __syncthreads();
    }

    const int* mrow = mask + n*LL*LL;
    #pragma unroll
    for (int ii = 0; ii < 8; ii++) {
        int q = q0 + 8*ty + ii;
        float* srow = g_s + (nh*LL + q)*LL;
        #pragma unroll
        for (int cc = 0; cc < 8; cc++) {
            int k = c0 + 8*tx + cc;
            float v = mrow[q*LL + k] ? acc[ii][cc]*SCALE : NEGV;
            srow[k] = v;
        }
    }
}

// ---------------------------------------------------------------------------
// K2b: row softmax over 1024 entries. grid = NB*HH*LL blocks, 256 threads.
// ---------------------------------------------------------------------------
__global__ __launch_bounds__(256) void softmax_kernel()
{
    int row = blockIdx.x;
    float4* p = reinterpret_cast<float4*>(g_s) + (size_t)row * 256;
    int tid = threadIdx.x;
    __shared__ float red[256];

    float4 v = p[tid];
    float m = fmaxf(fmaxf(v.x, v.y), fmaxf(v.z, v.w));
    red[tid] = m; __syncthreads();
    #pragma unroll
    for (int s = 128; s > 0; s >>= 1) {
        if (tid < s) red[tid] = fmaxf(red[tid], red[tid + s]);
        __syncthreads();
    }
    m = red[0];
    __syncthreads();

    float e0 = expf(v.x - m), e1 = expf(v.y - m);
    float e2 = expf(v.z - m), e3 = expf(v.w - m);
    red[tid] = e0 + e1 + e2 + e3; __syncthreads();
    #pragma unroll
    for (int s = 128; s > 0; s >>= 1) {
        if (tid < s) red[tid] += red[tid + s];
        __syncthreads();
    }
    float inv = 1.0f / red[0];
    p[tid] = make_float4(e0*inv, e1*inv, e2*inv, e3*inv);
}

// ---------------------------------------------------------------------------
// K2c: O[q][d] = sum_k P[q][k] V[k][d] per (n,h). grid (8, 32).
// ---------------------------------------------------------------------------
__global__ __launch_bounds__(256) void pv_kernel()
{
    __shared__ float As[128][17];
    __shared__ float Bs[16][128];
    int tid = threadIdx.x;
    int ty = tid >> 4, tx = tid & 15;
    int nh = blockIdx.y;
    int n = nh >> 4, h = nh & 15;
    int q0 = blockIdx.x * 128;

    float acc[8][8] = {};

    for (int k0 = 0; k0 < 1024; k0 += 16) {
        for (int i = tid; i < 2048; i += 256) {
            int r = i >> 4, kk = i & 15;
            As[r][kk] = g_s[(nh*LL + q0 + r)*LL + k0 + kk];
        }
        for (int i = tid; i < 2048; i += 256) {
            int kk = i >> 7, d = i & 127;
            Bs[kk][d] = g_v[((n*LL + k0 + kk)*HH + h)*DD + d];
        }
        __syncthreads();
        gemm_step<17, 128>(&As[0][0], &Bs[0][0], acc, ty, tx);
        __syncthreads();
    }

    #pragma unroll
    for (int ii = 0; ii < 8; ii++) {
        int q = q0 + 8*ty + ii;
        float* orow = g_o + ((n*LL + q)*HH + h)*DD;
        float4 o0 = make_float4(acc[ii][0], acc[ii][1], acc[ii][2], acc[ii][3]);
        float4 o1 = make_float4(acc[ii][4], acc[ii][5], acc[ii][6], acc[ii][7]);
        *reinterpret_cast<float4*>(&orow[8*tx])     = o0;
        *reinterpret_cast<float4*>(&orow[8*tx + 4]) = o1;
    }
}

// ---------------------------------------------------------------------------
// K3: out = X @ Wo^T + bo. X = g_o viewed (2048, 2048). grid (16, 16).
// ---------------------------------------------------------------------------
__global__ __launch_bounds__(256) void out_kernel(
    const float* __restrict__ Wo, const float* __restrict__ bo,
    float* __restrict__ out)
{
    __shared__ float As[128][17];
    __shared__ float Bs[16][132];
    int tid = threadIdx.x;
    int ty = tid >> 4, tx = tid & 15;
    int c0 = blockIdx.x * 128;
    int r0 = blockIdx.y * 128;

    float acc[8][8] = {};

    for (int k0 = 0; k0 < 2048; k0 += 16) {
        for (int i = tid; i < 2048; i += 256) {
            int r = i >> 4, kk = i & 15;
            As[r][kk] = g_o[(r0 + r)*2048 + k0 + kk];
        }
        for (int f = tid; f < 512; f += 256) {
            int c = f >> 2, q4 = (f & 3) * 4;
            float4 w = *reinterpret_cast<const float4*>(&Wo[(c0 + c)*2048 + k0 + q4]);
            Bs[q4+0][c] = w.x; Bs[q4+1][c] = w.y;
            Bs[q4+2][c] = w.z; Bs[q4+3][c] = w.w;
        }
        __syncthreads();
        gemm_step<17, 132>(&As[0][0], &Bs[0][0], acc, ty, tx);
        __syncthreads();
    }

    float4 bb0 = *reinterpret_cast<const float4*>(&bo[c0 + 8*tx]);
    float4 bb1 = *reinterpret_cast<const float4*>(&bo[c0 + 8*tx + 4]);
    #pragma unroll
    for (int ii = 0; ii < 8; ii++) {
        int r = r0 + 8*ty + ii;
        float4 o0 = make_float4(acc[ii][0]+bb0.x, acc[ii][1]+bb0.y,
                                acc[ii][2]+bb0.z, acc[ii][3]+bb0.w);
        float4 o1 = make_float4(acc[ii][4]+bb1.x, acc[ii][5]+bb1.y,
                                acc[ii][6]+bb1.z, acc[ii][7]+bb1.w);
        *reinterpret_cast<float4*>(&out[r*2048 + c0 + 8*tx])     = o0;
        *reinterpret_cast<float4*>(&out[r*2048 + c0 + 8*tx + 4]) = o1;
    }
}

// ---------------------------------------------------------------------------
// Launch: values, keys, queries, mask, Wv, Wk, Wq, Wo, bo
// ---------------------------------------------------------------------------
extern "C" void kernel_launch(void* const* d_in, const int* in_sizes, int n_in,
                              void* d_out, int out_size)
{
    const float* values  = (const float*)d_in[0];
    const float* keys    = (const float*)d_in[1];
    const float* queries = (const float*)d_in[2];
    const int*   mask    = (const int*)  d_in[3];
    const float* Wv      = (const float*)d_in[4];
    const float* Wk      = (const float*)d_in[5];
    const float* Wq      = (const float*)d_in[6];
    const float* Wo      = (const float*)d_in[7];
    const float* bo      = (const float*)d_in[8];
    float* out = (float*)d_out;

    rope_tab_kernel<<<LL, 64>>>();
    proj_kernel<<<dim3(256, 3), 256>>>(queries, keys, values, Wq, Wk, Wv);
    score_kernel<<<dim3(8, 8, 32), 256>>>(mask);
    softmax_kernel<<<NB*HH*LL, 256>>>();
    pv_kernel<<<dim3(8, 32), 256>>>();
    out_kernel<<<dim3(16, 16), 256>>>(Wo, bo, out);
}

// round 2
// speedup vs baseline: 1.5816x; 1.5816x over previous
#include <cuda_runtime.h>
#include <stdint.h>

// Problem constants
#define NB 2
#define LL 1024
#define EE 2048
#define HH 16
#define DD 128
#define SCALE 0.02209708691207961f   // 1/sqrt(2048)
#define NEGV  -1e20f

// Scratch (device statics; no allocations allowed)
__device__ float g_q[NB*LL*EE];
__device__ float g_k[NB*LL*EE];
__device__ float g_v[NB*LL*EE];
__device__ float g_s[NB*HH*LL*LL];   // 134 MB score matrix
__device__ float g_o[NB*LL*EE];      // attention output (n,l,h,d)
__device__ float g_cos[LL*64];
__device__ float g_sin[LL*64];

// tf32 round-to-nearest (unbiased; avoids truncation bias in mma operands)
__device__ __forceinline__ float tf32r(float x) {
    uint32_t u;
    asm("cvt.rna.tf32.f32 %0, %1;" : "=r"(u) : "f"(x));
    return __uint_as_float(u);
}

// ---------------------------------------------------------------------------
// K0: RoPE sin/cos table
// ---------------------------------------------------------------------------
__global__ void rope_tab_kernel() {
    int l = blockIdx.x;
    int j = threadIdx.x;
    float expo = (float)(2 * j) / 128.0f;
    float invf = 1.0f / powf(10000.0f, expo);
    float a = (float)l * invf;
    g_cos[l*64 + j] = cosf(a);
    g_sin[l*64 + j] = sinf(a);
}

// ---------------------------------------------------------------------------
// tf32 mma helpers. Block = 256 threads = 8 warps (wr = wid>>2 in {0,1},
// wc = wid&3 in {0..3}). Warp tile 64x32 = 4x4 m16n8k8 tiles.
// A smem: [128][36] row-major (m, k). B smem: [32][133] (k, n).
// ---------------------------------------------------------------------------
#define AST 36
#define BST 133

__device__ __forceinline__ void mma8(float* d, const uint32_t* a, const uint32_t* b) {
    asm volatile(
        "mma.sync.aligned.m16n8k8.row.col.f32.tf32.tf32.f32 "
        "{%0,%1,%2,%3}, {%4,%5,%6,%7}, {%8,%9}, {%0,%1,%2,%3};"
        : "+f"(d[0]), "+f"(d[1]), "+f"(d[2]), "+f"(d[3])
        : "r"(a[0]), "r"(a[1]), "r"(a[2]), "r"(a[3]), "r"(b[0]), "r"(b[1]));
}

// one k8 step: tr = lane>>2, tk = lane&3
__device__ __forceinline__ void mma_k8(const float* __restrict__ As,
                                       const float* __restrict__ Bs,
                                       int k, float d[4][4][4],
                                       int tr, int tk, int wr, int wc)
{
    uint32_t a[4][4], b[4][2];
    #pragma unroll
    for (int mt = 0; mt < 4; mt++) {
        const float* ap = As + (wr*64 + mt*16 + tr)*AST + k + tk;
        a[mt][0] = __float_as_uint(ap[0]);
        a[mt][1] = __float_as_uint(ap[8*AST]);
        a[mt][2] = __float_as_uint(ap[4]);
        a[mt][3] = __float_as_uint(ap[8*AST + 4]);
    }
    #pragma unroll
    for (int nt = 0; nt < 4; nt++) {
        const float* bp = Bs + (k + tk)*BST + wc*32 + nt*8 + tr;
        b[nt][0] = __float_as_uint(bp[0]);
        b[nt][1] = __float_as_uint(bp[4*BST]);
    }
    #pragma unroll
    for (int mt = 0; mt < 4; mt++)
        #pragma unroll
        for (int nt = 0; nt < 4; nt++)
            mma8(d[mt][nt], a[mt], b[nt]);
}

// ---------------------------------------------------------------------------
// K1: fused RoPE + per-head projection (rows = (n,l,h), 32768x128x128)
// grid (256, 3): y = 0:q(rope) 1:k(rope) 2:v
// ---------------------------------------------------------------------------
__global__ __launch_bounds__(256) void proj_kernel(
    const float* __restrict__ qin, const float* __restrict__ kin,
    const float* __restrict__ vin,
    const float* __restrict__ Wq, const float* __restrict__ Wk,
    const float* __restrict__ Wv)
{
    __shared__ float As[128][AST];
    __shared__ float Bs[32][BST];
    int tid = threadIdx.x;
    int lane = tid & 31, wid = tid >> 5;
    int tr = lane >> 2, tk = lane & 3;
    int wr = wid >> 2, wc = wid & 3;
    int tensor = blockIdx.y;
    const float* X = (tensor == 0) ? qin : (tensor == 1) ? kin : vin;
    const float* W = (tensor == 0) ? Wq  : (tensor == 1) ? Wk  : Wv;
    float* OUT     = (tensor == 0) ? g_q : (tensor == 1) ? g_k : g_v;
    bool rope = (tensor < 2);
    int base = blockIdx.x * 128;

    float d[4][4][4] = {};

    for (int k0 = 0; k0 < 128; k0 += 32) {
        // A: roped rows, tf32-rounded
        for (int i = tid; i < 128*32; i += 256) {
            int r = i >> 5, kk = i & 31;
            int rg = base + r;
            int dd = k0 + kk;
            float val;
            if (rope) {
                int l = (rg >> 4) & 1023;
                int j = dd & 63;
                val = X[rg*128 + dd]        * g_cos[l*64 + j]
                    + X[rg*128 + 127 - dd]  * g_sin[l*64 + j];
            } else {
                val = X[rg*128 + dd];
            }
            As[r][kk] = tf32r(val);
        }
        // B: Bs[kk][o] = W[o][k0+kk]
        for (int f = tid; f < 1024; f += 256) {
            int o = f >> 3, q4 = (f & 7) * 4;
            float4 w = *reinterpret_cast<const float4*>(&W[o*128 + k0 + q4]);
            Bs[q4+0][o] = tf32r(w.x); Bs[q4+1][o] = tf32r(w.y);
            Bs[q4+2][o] = tf32r(w.z); Bs[q4+3][o] = tf32r(w.w);
        }
        __syncthreads();
        #pragma unroll
        for (int ks = 0; ks < 32; ks += 8)
            mma_k8(&As[0][0], &Bs[0][0], ks, d, tr, tk, wr, wc);
        __syncthreads();
    }

    #pragma unroll
    for (int mt = 0; mt < 4; mt++) {
        int rg = base + wr*64 + mt*16 + tr;
        #pragma unroll
        for (int nt = 0; nt < 4; nt++) {
            int col = wc*32 + nt*8 + tk*2;
            *reinterpret_cast<float2*>(&OUT[rg*128 + col]) =
                make_float2(d[mt][nt][0], d[mt][nt][1]);
            *reinterpret_cast<float2*>(&OUT[(rg+8)*128 + col]) =
                make_float2(d[mt][nt][2], d[mt][nt][3]);
        }
    }
}

// ---------------------------------------------------------------------------
// K2a: scores S = mask ? (q.k)*SCALE : -1e20. grid (8, 8, 32)
// ---------------------------------------------------------------------------
__global__ __launch_bounds__(256) void score_kernel(const int* __restrict__ mask)
{
    __shared__ float As[128][AST];
    __shared__ float Bs[32][BST];
    int tid = threadIdx.x;
    int lane = tid & 31, wid = tid >> 5;
    int tr = lane >> 2, tk = lane & 3;
    int wr = wid >> 2, wc = wid & 3;
    int nh = blockIdx.z;
    int n = nh >> 4, h = nh & 15;
    int q0 = blockIdx.x * 128;
    int c0 = blockIdx.y * 128;

    float d[4][4][4] = {};

    for (int k0 = 0; k0 < 128; k0 += 32) {
        for (int i = tid; i < 4096; i += 256) {
            int r = i >> 5, kk = i & 31;
            As[r][kk] = tf32r(g_q[((n*LL + q0 + r)*HH + h)*DD + k0 + kk]);
        }
        for (int i = tid; i < 4096; i += 256) {
            int c = i >> 5, kk = i & 31;
            Bs[kk][c] = tf32r(g_k[((n*LL + c0 + c)*HH + h)*DD + k0 + kk]);
        }
        __syncthreads();
        #pragma unroll
        for (int ks = 0; ks < 32; ks += 8)
            mma_k8(&As[0][0], &Bs[0][0], ks, d, tr, tk, wr, wc);
        __syncthreads();
    }

    const int* mrow = mask + n*LL*LL;
    #pragma unroll
    for (int mt = 0; mt < 4; mt++) {
        int q = q0 + wr*64 + mt*16 + tr;
        #pragma unroll
        for (int nt = 0; nt < 4; nt++) {
            int kc = c0 + wc*32 + nt*8 + tk*2;
            int2 m0 = *reinterpret_cast<const int2*>(&mrow[q*LL + kc]);
            int2 m1 = *reinterpret_cast<const int2*>(&mrow[(q+8)*LL + kc]);
            float2 v0 = make_float2(m0.x ? d[mt][nt][0]*SCALE : NEGV,
                                    m0.y ? d[mt][nt][1]*SCALE : NEGV);
            float2 v1 = make_float2(m1.x ? d[mt][nt][2]*SCALE : NEGV,
                                    m1.y ? d[mt][nt][3]*SCALE : NEGV);
            *reinterpret_cast<float2*>(&g_s[((size_t)nh*LL + q)*LL + kc])   = v0;
            *reinterpret_cast<float2*>(&g_s[((size_t)nh*LL + q+8)*LL + kc]) = v1;
        }
    }
}

// ---------------------------------------------------------------------------
// K2b: warp-per-row softmax over 1024 entries. grid = 4096, block 256 (8 rows)
// ---------------------------------------------------------------------------
__global__ __launch_bounds__(256) void softmax_kernel()
{
    int wid = threadIdx.x >> 5, lane = threadIdx.x & 31;
    int row = blockIdx.x * 8 + wid;
    float4* p = reinterpret_cast<float4*>(g_s) + (size_t)row * 256;

    float4 v[8];
    float m = -3.4e38f;
    #pragma unroll
    for (int j = 0; j < 8; j++) {
        v[j] = p[lane + j*32];
        m = fmaxf(m, fmaxf(fmaxf(v[j].x, v[j].y), fmaxf(v[j].z, v[j].w)));
    }
    #pragma unroll
    for (int off = 16; off; off >>= 1)
        m = fmaxf(m, __shfl_xor_sync(0xffffffffu, m, off));

    float s = 0.0f;
    #pragma unroll
    for (int j = 0; j < 8; j++) {
        v[j].x = __expf(v[j].x - m); v[j].y = __expf(v[j].y - m);
        v[j].z = __expf(v[j].z - m); v[j].w = __expf(v[j].w - m);
        s += (v[j].x + v[j].y) + (v[j].z + v[j].w);
    }
    #pragma unroll
    for (int off = 16; off; off >>= 1)
        s += __shfl_xor_sync(0xffffffffu, s, off);
    float inv = 1.0f / s;

    #pragma unroll
    for (int j = 0; j < 8; j++) {
        v[j].x *= inv; v[j].y *= inv; v[j].z *= inv; v[j].w *= inv;
        p[lane + j*32] = v[j];
    }
}

// ---------------------------------------------------------------------------
// K2c: O = P @ V per (n,h). grid (8, 32)
// ---------------------------------------------------------------------------
__global__ __launch_bounds__(256) void pv_kernel()
{
    __shared__ float As[128][AST];
    __shared__ float Bs[32][BST];
    int tid = threadIdx.x;
    int lane = tid & 31, wid = tid >> 5;
    int tr = lane >> 2, tk = lane & 3;
    int wr = wid >> 2, wc = wid & 3;
    int nh = blockIdx.y;
    int n = nh >> 4, h = nh & 15;
    int q0 = blockIdx.x * 128;

    float d[4][4][4] = {};

    for (int k0 = 0; k0 < 1024; k0 += 32) {
        for (int i = tid; i < 4096; i += 256) {
            int r = i >> 5, kk = i & 31;
            As[r][kk] = tf32r(g_s[((size_t)nh*LL + q0 + r)*LL + k0 + kk]);
        }
        for (int i = tid; i < 4096; i += 256) {
            int kk = i >> 7, dd = i & 127;
            Bs[kk][dd] = tf32r(g_v[((n*LL + k0 + kk)*HH + h)*DD + dd]);
        }
        __syncthreads();
        #pragma unroll
        for (int ks = 0; ks < 32; ks += 8)
            mma_k8(&As[0][0], &Bs[0][0], ks, d, tr, tk, wr, wc);
        __syncthreads();
    }

    #pragma unroll
    for (int mt = 0; mt < 4; mt++) {
        int q = q0 + wr*64 + mt*16 + tr;
        #pragma unroll
        for (int nt = 0; nt < 4; nt++) {
            int col = wc*32 + nt*8 + tk*2;
            float* o0 = g_o + ((n*LL + q)*HH + h)*DD + col;
            float* o1 = g_o + ((n*LL + q+8)*HH + h)*DD + col;
            *reinterpret_cast<float2*>(o0) = make_float2(d[mt][nt][0], d[mt][nt][1]);
            *reinterpret_cast<float2*>(o1) = make_float2(d[mt][nt][2], d[mt][nt][3]);
        }
    }
}

// ---------------------------------------------------------------------------
// K3: out = X @ Wo^T + bo, X = g_o as (2048, 2048). grid (16, 16)
// ---------------------------------------------------------------------------
__global__ __launch_bounds__(256) void out_kernel(
    const float* __restrict__ Wo, const float* __restrict__ bo,
    float* __restrict__ out)
{
    __shared__ float As[128][AST];
    __shared__ float Bs[32][BST];
    int tid = threadIdx.x;
    int lane = tid & 31, wid = tid >> 5;
    int tr = lane >> 2, tk = lane & 3;
    int wr = wid >> 2, wc = wid & 3;
    int c0 = blockIdx.x * 128;
    int r0 = blockIdx.y * 128;

    float d[4][4][4] = {};

    for (int k0 = 0; k0 < 2048; k0 += 32) {
        for (int i = tid; i < 4096; i += 256) {
            int r = i >> 5, kk = i & 31;
            As[r][kk] = tf32r(g_o[(r0 + r)*2048 + k0 + kk]);
        }
        for (int f = tid; f < 1024; f += 256) {
            int c = f >> 3, q4 = (f & 7) * 4;
            float4 w = *reinterpret_cast<const float4*>(&Wo[(c0 + c)*2048 + k0 + q4]);
            Bs[q4+0][c] = tf32r(w.x); Bs[q4+1][c] = tf32r(w.y);
            Bs[q4+2][c] = tf32r(w.z); Bs[q4+3][c] = tf32r(w.w);
        }
        __syncthreads();
        #pragma unroll
        for (int ks = 0; ks < 32; ks += 8)
            mma_k8(&As[0][0], &Bs[0][0], ks, d, tr, tk, wr, wc);
        __syncthreads();
    }

    #pragma unroll
    for (int mt = 0; mt < 4; mt++) {
        int r = r0 + wr*64 + mt*16 + tr;
        #pragma unroll
        for (int nt = 0; nt < 4; nt++) {
            int col = c0 + wc*32 + nt*8 + tk*2;
            float2 bb = *reinterpret_cast<const float2*>(&bo[col]);
            *reinterpret_cast<float2*>(&out[r*2048 + col]) =
                make_float2(d[mt][nt][0] + bb.x, d[mt][nt][1] + bb.y);
            *reinterpret_cast<float2*>(&out[(r+8)*2048 + col]) =
                make_float2(d[mt][nt][2] + bb.x, d[mt][nt][3] + bb.y);
        }
    }
}

// ---------------------------------------------------------------------------
// Launch: values, keys, queries, mask, Wv, Wk, Wq, Wo, bo
// ---------------------------------------------------------------------------
extern "C" void kernel_launch(void* const* d_in, const int* in_sizes, int n_in,
                              void* d_out, int out_size)
{
    const float* values  = (const float*)d_in[0];
    const float* keys    = (const float*)d_in[1];
    const float* queries = (const float*)d_in[2];
    const int*   mask    = (const int*)  d_in[3];
    const float* Wv      = (const float*)d_in[4];
    const float* Wk      = (const float*)d_in[5];
    const float* Wq      = (const float*)d_in[6];
    const float* Wo      = (const float*)d_in[7];
    const float* bo      = (const float*)d_in[8];
    float* out = (float*)d_out;

    rope_tab_kernel<<<LL, 64>>>();
    proj_kernel<<<dim3(256, 3), 256>>>(queries, keys, values, Wq, Wk, Wv);
    score_kernel<<<dim3(8, 8, 32), 256>>>(mask);
    softmax_kernel<<<NB*HH*LL/8, 256>>>();
    pv_kernel<<<dim3(8, 32), 256>>>();
    out_kernel<<<dim3(16, 16), 256>>>(Wo, bo, out);
}

// round 4
// speedup vs baseline: 3.0251x; 1.9126x over previous
#include <cuda_runtime.h>
#include <stdint.h>

// Problem constants
#define NB 2
#define LL 1024
#define HH 16
#define DD 128
#define SCALE 0.02209708691207961f   // 1/sqrt(2048)
#define NEGV  -1e20f

// Scratch (device statics; no allocations allowed)
__device__ float g_q[NB*LL*HH*DD];
__device__ float g_k[NB*LL*HH*DD];
__device__ float g_v[NB*LL*HH*DD];
__device__ float g_s[NB*HH*LL*LL];   // 134 MB score matrix
__device__ float g_o[NB*LL*HH*DD];   // attention output (n,l,h,d)
__device__ float g_cos[LL*64];
__device__ float g_sin[LL*64];

// tf32 round-to-nearest (unbiased; avoids truncation bias in mma operands)
__device__ __forceinline__ float tf32r(float x) {
    uint32_t u;
    asm("cvt.rna.tf32.f32 %0, %1;" : "=r"(u) : "f"(x));
    return __uint_as_float(u);
}

// ---------------------------------------------------------------------------
// Tiling: block 128x128, BK=32, 8 warps, warp tile 64x32 (4x4 m16n8k8).
// Double-buffered dynamic smem.
// ---------------------------------------------------------------------------
#define AST 36
#define BST 133
#define AW (128*AST)                 // 4608 words
#define BW (32*BST)                  // 4256 words
#define SMEM_WORDS (2*(AW+BW))       // 17728 words
#define SMEM_BYTES (SMEM_WORDS*4)    // 70912 bytes

__device__ __forceinline__ void mma8(float* d, const uint32_t* a, const uint32_t* b) {
    asm volatile(
        "mma.sync.aligned.m16n8k8.row.col.f32.tf32.tf32.f32 "
        "{%0,%1,%2,%3}, {%4,%5,%6,%7}, {%8,%9}, {%0,%1,%2,%3};"
        : "+f"(d[0]), "+f"(d[1]), "+f"(d[2]), "+f"(d[3])
        : "r"(a[0]), "r"(a[1]), "r"(a[2]), "r"(a[3]), "r"(b[0]), "r"(b[1]));
}

__device__ __forceinline__ void mma_k8(const float* __restrict__ As,
                                       const float* __restrict__ Bs,
                                       int k, float d[4][4][4],
                                       int tr, int tk, int wr, int wc)
{
    uint32_t a[4][4], b[4][2];
    #pragma unroll
    for (int mt = 0; mt < 4; mt++) {
        const float* ap = As + (wr*64 + mt*16 + tr)*AST + k + tk;
        a[mt][0] = __float_as_uint(ap[0]);
        a[mt][1] = __float_as_uint(ap[8*AST]);
        a[mt][2] = __float_as_uint(ap[4]);
        a[mt][3] = __float_as_uint(ap[8*AST + 4]);
    }
    #pragma unroll
    for (int nt = 0; nt < 4; nt++) {
        const float* bp = Bs + (k + tk)*BST + wc*32 + nt*8 + tr;
        b[nt][0] = __float_as_uint(bp[0]);
        b[nt][1] = __float_as_uint(bp[4*BST]);
    }
    #pragma unroll
    for (int mt = 0; mt < 4; mt++)
        #pragma unroll
        for (int nt = 0; nt < 4; nt++)
            mma8(d[mt][nt], a[mt], b[nt]);
}

// ---------------------------------------------------------------------------
// Staging helpers. Tiles: A = 128 rows x 32 k, B = 128 cols x 32 k.
// All sources K-contiguous unless noted.
// ---------------------------------------------------------------------------
__device__ __forceinline__ void ldg_k(float4 v[4], const float* __restrict__ g,
                                      int stride, int tid) {
    #pragma unroll
    for (int t = 0; t < 4; t++) {
        int i = tid + t*256;
        int r = i >> 3, k4 = (i & 7) << 2;
        v[t] = *reinterpret_cast<const float4*>(g + (size_t)r*stride + k4);
    }
}
__device__ __forceinline__ void sts_A(float* As, const float4 v[4], int tid) {
    #pragma unroll
    for (int t = 0; t < 4; t++) {
        int i = tid + t*256;
        int r = i >> 3, k4 = (i & 7) << 2;
        *reinterpret_cast<float4*>(As + r*AST + k4) =
            make_float4(tf32r(v[t].x), tf32r(v[t].y), tf32r(v[t].z), tf32r(v[t].w));
    }
}
__device__ __forceinline__ void sts_B(float* Bs, const float4 v[4], int tid) {
    #pragma unroll
    for (int t = 0; t < 4; t++) {
        int i = tid + t*256;
        int c = i >> 3, k4 = (i & 7) << 2;
        Bs[(k4+0)*BST + c] = tf32r(v[t].x);
        Bs[(k4+1)*BST + c] = tf32r(v[t].y);
        Bs[(k4+2)*BST + c] = tf32r(v[t].z);
        Bs[(k4+3)*BST + c] = tf32r(v[t].w);
    }
}

// RoPE-fused A load (q/k projection). d in [0,124], tables tiled x2 over 64.
__device__ __forceinline__ void ldg_rope(float4 v[4], const float* __restrict__ X,
                                         int base, int k0, int tid) {
    #pragma unroll
    for (int t = 0; t < 4; t++) {
        int i = tid + t*256;
        int r = i >> 3, k4 = (i & 7) << 2;
        int rg = base + r;
        int d = k0 + k4;
        int l = (rg >> 4) & 1023;
        const float* xr = X + (size_t)rg*128;
        float4 f = *reinterpret_cast<const float4*>(xr + d);
        float4 m = *reinterpret_cast<const float4*>(xr + 124 - d);
        float4 c = *reinterpret_cast<const float4*>(g_cos + l*64 + (d & 63));
        float4 s = *reinterpret_cast<const float4*>(g_sin + l*64 + (d & 63));
        v[t] = make_float4(f.x*c.x + m.w*s.x, f.y*c.y + m.z*s.y,
                           f.z*c.z + m.y*s.z, f.w*c.w + m.x*s.w);
    }
}

// pv B tile: source rows = k (stride 2048), cols contiguous (MN-major).
__device__ __forceinline__ void ldg_pvB(float vb[16], const float* __restrict__ g,
                                        int tid) {
    #pragma unroll
    for (int t = 0; t < 16; t++) {
        int i = tid + t*256;
        int kk = i >> 7, dd = i & 127;
        vb[t] = g[(size_t)kk*2048 + dd];
    }
}
__device__ __forceinline__ void sts_pvB(float* Bs, const float vb[16], int tid) {
    #pragma unroll
    for (int t = 0; t < 16; t++) {
        int i = tid + t*256;
        int kk = i >> 7, dd = i & 127;
        Bs[kk*BST + dd] = tf32r(vb[t]);
    }
}

// ---------------------------------------------------------------------------
// K0: RoPE sin/cos table
// ---------------------------------------------------------------------------
__global__ void rope_tab_kernel() {
    int l = blockIdx.x;
    int j = threadIdx.x;
    float expo = (float)(2 * j) / 128.0f;
    float invf = 1.0f / powf(10000.0f, expo);
    float a = (float)l * invf;
    g_cos[l*64 + j] = cosf(a);
    g_sin[l*64 + j] = sinf(a);
}

// ---------------------------------------------------------------------------
// K1: fused RoPE + per-head projection (32768x128x128). grid (256, 3)
// ---------------------------------------------------------------------------
__global__ __launch_bounds__(256) void proj_kernel(
    const float* __restrict__ qin, const float* __restrict__ kin,
    const float* __restrict__ vin,
    const float* __restrict__ Wq, const float* __restrict__ Wk,
    const float* __restrict__ Wv)
{
    extern __shared__ float dsm[];
    float *A0 = dsm, *A1 = dsm + AW, *B0 = dsm + 2*AW, *B1 = dsm + 2*AW + BW;
    int tid = threadIdx.x;
    int lane = tid & 31, wid = tid >> 5;
    int tr = lane >> 2, tk = lane & 3;
    int wr = wid >> 2, wc = wid & 3;
    int tensor = blockIdx.y;
    const float* X = (tensor == 0) ? qin : (tensor == 1) ? kin : vin;
    const float* W = (tensor == 0) ? Wq  : (tensor == 1) ? Wk  : Wv;
    float* OUT     = (tensor == 0) ? g_q : (tensor == 1) ? g_k : g_v;
    bool rope = (tensor < 2);
    int base = blockIdx.x * 128;

    float d[4][4][4] = {};
    float4 va[4], vb[4];

    if (rope) ldg_rope(va, X, base, 0, tid);
    else      ldg_k(va, X + (size_t)base*128, 128, tid);
    ldg_k(vb, W, 128, tid);
    sts_A(A0, va, tid); sts_B(B0, vb, tid);
    __syncthreads();

    #pragma unroll
    for (int t = 0; t < 4; t++) {
        if (t < 3) {
            int k0 = (t+1)*32;
            if (rope) ldg_rope(va, X, base, k0, tid);
            else      ldg_k(va, X + (size_t)base*128 + k0, 128, tid);
            ldg_k(vb, W + k0, 128, tid);
        }
        const float* As = (t & 1) ? A1 : A0;
        const float* Bs = (t & 1) ? B1 : B0;
        #pragma unroll
        for (int ks = 0; ks < 32; ks += 8)
            mma_k8(As, Bs, ks, d, tr, tk, wr, wc);
        if (t < 3) {
            sts_A((t & 1) ? A0 : A1, va, tid);
            sts_B((t & 1) ? B0 : B1, vb, tid);
        }
        __syncthreads();
    }

    #pragma unroll
    for (int mt = 0; mt < 4; mt++) {
        int rg = base + wr*64 + mt*16 + tr;
        #pragma unroll
        for (int nt = 0; nt < 4; nt++) {
            int col = wc*32 + nt*8 + tk*2;
            *reinterpret_cast<float2*>(&OUT[rg*128 + col]) =
                make_float2(d[mt][nt][0], d[mt][nt][1]);
            *reinterpret_cast<float2*>(&OUT[(rg+8)*128 + col]) =
                make_float2(d[mt][nt][2], d[mt][nt][3]);
        }
    }
}

// ---------------------------------------------------------------------------
// K2a: scores S = mask ? (q.k)*SCALE : -1e20. grid (8, 8, 32)
// ---------------------------------------------------------------------------
__global__ __launch_bounds__(256) void score_kernel(const int* __restrict__ mask)
{
    extern __shared__ float dsm[];
    float *A0 = dsm, *A1 = dsm + AW, *B0 = dsm + 2*AW, *B1 = dsm + 2*AW + BW;
    int tid = threadIdx.x;
    int lane = tid & 31, wid = tid >> 5;
    int tr = lane >> 2, tk = lane & 3;
    int wr = wid >> 2, wc = wid & 3;
    int nh = blockIdx.z;
    int n = nh >> 4, h = nh & 15;
    int q0 = blockIdx.x * 128;
    int c0 = blockIdx.y * 128;
    const float* Ag = g_q + ((size_t)(n*LL + q0)*HH + h)*DD;
    const float* Bg = g_k + ((size_t)(n*LL + c0)*HH + h)*DD;

    float d[4][4][4] = {};
    float4 va[4], vb[4];

    ldg_k(va, Ag, HH*DD, tid);
    ldg_k(vb, Bg, HH*DD, tid);
    sts_A(A0, va, tid); sts_B(B0, vb, tid);
    __syncthreads();

    #pragma unroll
    for (int t = 0; t < 4; t++) {
        if (t < 3) {
            int k0 = (t+1)*32;
            ldg_k(va, Ag + k0, HH*DD, tid);
            ldg_k(vb, Bg + k0, HH*DD, tid);
        }
        const float* As = (t & 1) ? A1 : A0;
        const float* Bs = (t & 1) ? B1 : B0;
        #pragma unroll
        for (int ks = 0; ks < 32; ks += 8)
            mma_k8(As, Bs, ks, d, tr, tk, wr, wc);
        if (t < 3) {
            sts_A((t & 1) ? A0 : A1, va, tid);
            sts_B((t & 1) ? B0 : B1, vb, tid);
        }
        __syncthreads();
    }

    const int* mrow = mask + (size_t)n*LL*LL;
    #pragma unroll
    for (int mt = 0; mt < 4; mt++) {
        int q = q0 + wr*64 + mt*16 + tr;
        #pragma unroll
        for (int nt = 0; nt < 4; nt++) {
            int kc = c0 + wc*32 + nt*8 + tk*2;
            int2 m0 = *reinterpret_cast<const int2*>(&mrow[(size_t)q*LL + kc]);
            int2 m1 = *reinterpret_cast<const int2*>(&mrow[(size_t)(q+8)*LL + kc]);
            float2 v0 = make_float2(m0.x ? d[mt][nt][0]*SCALE : NEGV,
                                    m0.y ? d[mt][nt][1]*SCALE : NEGV);
            float2 v1 = make_float2(m1.x ? d[mt][nt][2]*SCALE : NEGV,
                                    m1.y ? d[mt][nt][3]*SCALE : NEGV);
            *reinterpret_cast<float2*>(&g_s[((size_t)nh*LL + q)*LL + kc])   = v0;
            *reinterpret_cast<float2*>(&g_s[((size_t)nh*LL + q+8)*LL + kc]) = v1;
        }
    }
}

// ---------------------------------------------------------------------------
// K2b: warp-per-row softmax over 1024 entries. grid 4096, block 256 (8 rows)
// ---------------------------------------------------------------------------
__global__ __launch_bounds__(256) void softmax_kernel()
{
    int wid = threadIdx.x >> 5, lane = threadIdx.x & 31;
    int row = blockIdx.x * 8 + wid;
    float4* p = reinterpret_cast<float4*>(g_s) + (size_t)row * 256;

    float4 v[8];
    float m = -3.4e38f;
    #pragma unroll
    for (int j = 0; j < 8; j++) {
        v[j] = p[lane + j*32];
        m = fmaxf(m, fmaxf(fmaxf(v[j].x, v[j].y), fmaxf(v[j].z, v[j].w)));
    }
    #pragma unroll
    for (int off = 16; off; off >>= 1)
        m = fmaxf(m, __shfl_xor_sync(0xffffffffu, m, off));

    float s = 0.0f;
    #pragma unroll
    for (int j = 0; j < 8; j++) {
        v[j].x = __expf(v[j].x - m); v[j].y = __expf(v[j].y - m);
        v[j].z = __expf(v[j].z - m); v[j].w = __expf(v[j].w - m);
        s += (v[j].x + v[j].y) + (v[j].z + v[j].w);
    }
    #pragma unroll
    for (int off = 16; off; off >>= 1)
        s += __shfl_xor_sync(0xffffffffu, s, off);
    float inv = 1.0f / s;

    #pragma unroll
    for (int j = 0; j < 8; j++) {
        v[j].x *= inv; v[j].y *= inv; v[j].z *= inv; v[j].w *= inv;
        p[lane + j*32] = v[j];
    }
}

// ---------------------------------------------------------------------------
// K2c: O = P @ V per (n,h). grid (8, 32). K = 1024.
// ---------------------------------------------------------------------------
__global__ __launch_bounds__(256) void pv_kernel()
{
    extern __shared__ float dsm[];
    float *A0 = dsm, *A1 = dsm + AW, *B0 = dsm + 2*AW, *B1 = dsm + 2*AW + BW;
    int tid = threadIdx.x;
    int lane = tid & 31, wid = tid >> 5;
    int tr = lane >> 2, tk = lane & 3;
    int wr = wid >> 2, wc = wid & 3;
    int nh = blockIdx.y;
    int n = nh >> 4, h = nh & 15;
    int q0 = blockIdx.x * 128;
    const float* Ag = g_s + ((size_t)nh*LL + q0)*LL;
    const float* Bg = g_v + ((size_t)n*LL*HH + h)*DD;   // + k*2048 + dd

    float d[4][4][4] = {};
    float4 va[4];
    float vb[16];

    ldg_k(va, Ag, LL, tid);
    ldg_pvB(vb, Bg, tid);
    sts_A(A0, va, tid); sts_pvB(B0, vb, tid);
    __syncthreads();

    for (int t = 0; t < 32; t++) {
        if (t < 31) {
            int k0 = (t+1)*32;
            ldg_k(va, Ag + k0, LL, tid);
            ldg_pvB(vb, Bg + (size_t)k0*2048, tid);
        }
        const float* As = (t & 1) ? A1 : A0;
        const float* Bs = (t & 1) ? B1 : B0;
        #pragma unroll
        for (int ks = 0; ks < 32; ks += 8)
            mma_k8(As, Bs, ks, d, tr, tk, wr, wc);
        if (t < 31) {
            sts_A((t & 1) ? A0 : A1, va, tid);
            sts_pvB((t & 1) ? B0 : B1, vb, tid);
        }
        __syncthreads();
    }

    #pragma unroll
    for (int mt = 0; mt < 4; mt++) {
        int q = q0 + wr*64 + mt*16 + tr;
        #pragma unroll
        for (int nt = 0; nt < 4; nt++) {
            int col = wc*32 + nt*8 + tk*2;
            float* o0 = g_o + ((size_t)(n*LL + q)*HH + h)*DD + col;
            float* o1 = g_o + ((size_t)(n*LL + q+8)*HH + h)*DD + col;
            *reinterpret_cast<float2*>(o0) = make_float2(d[mt][nt][0], d[mt][nt][1]);
            *reinterpret_cast<float2*>(o1) = make_float2(d[mt][nt][2], d[mt][nt][3]);
        }
    }
}

// ---------------------------------------------------------------------------
// K3: out = X @ Wo^T + bo, X = g_o as (2048, 2048). grid (16, 16). K = 2048.
// ---------------------------------------------------------------------------
__global__ __launch_bounds__(256) void out_kernel(
    const float* __restrict__ Wo, const float* __restrict__ bo,
    float* __restrict__ out)
{
    extern __shared__ float dsm[];
    float *A0 = dsm, *A1 = dsm + AW, *B0 = dsm + 2*AW, *B1 = dsm + 2*AW + BW;
    int tid = threadIdx.x;
    int lane = tid & 31, wid = tid >> 5;
    int tr = lane >> 2, tk = lane & 3;
    int wr = wid >> 2, wc = wid & 3;
    int c0 = blockIdx.x * 128;
    int r0 = blockIdx.y * 128;
    const float* Ag = g_o + (size_t)r0*2048;
    const float* Bg = Wo + (size_t)c0*2048;

    float d[4][4][4] = {};
    float4 va[4], vb[4];

    ldg_k(va, Ag, 2048, tid);
    ldg_k(vb, Bg, 2048, tid);
    sts_A(A0, va, tid); sts_B(B0, vb, tid);
    __syncthreads();

    for (int t = 0; t < 64; t++) {
        if (t < 63) {
            int k0 = (t+1)*32;
            ldg_k(va, Ag + k0, 2048, tid);
            ldg_k(vb, Bg + k0, 2048, tid);
        }
        const float* As = (t & 1) ? A1 : A0;
        const float* Bs = (t & 1) ? B1 : B0;
        #pragma unroll
        for (int ks = 0; ks < 32; ks += 8)
            mma_k8(As, Bs, ks, d, tr, tk, wr, wc);
        if (t < 63) {
            sts_A((t & 1) ? A0 : A1, va, tid);
            sts_B((t & 1) ? B0 : B1, vb, tid);
        }
        __syncthreads();
    }

    #pragma unroll
    for (int mt = 0; mt < 4; mt++) {
        int r = r0 + wr*64 + mt*16 + tr;
        #pragma unroll
        for (int nt = 0; nt < 4; nt++) {
            int col = c0 + wc*32 + nt*8 + tk*2;
            float2 bb = *reinterpret_cast<const float2*>(&bo[col]);
            *reinterpret_cast<float2*>(&out[(size_t)r*2048 + col]) =
                make_float2(d[mt][nt][0] + bb.x, d[mt][nt][1] + bb.y);
            *reinterpret_cast<float2*>(&out[(size_t)(r+8)*2048 + col]) =
                make_float2(d[mt][nt][2] + bb.x, d[mt][nt][3] + bb.y);
        }
    }
}

// ---------------------------------------------------------------------------
// Launch: values, keys, queries, mask, Wv, Wk, Wq, Wo, bo
// ---------------------------------------------------------------------------
extern "C" void kernel_launch(void* const* d_in, const int* in_sizes, int n_in,
                              void* d_out, int out_size)
{
    const float* values  = (const float*)d_in[0];
    const float* keys    = (const float*)d_in[1];
    const float* queries = (const float*)d_in[2];
    const int*   mask    = (const int*)  d_in[3];
    const float* Wv      = (const float*)d_in[4];
    const float* Wk      = (const float*)d_in[5];
    const float* Wq      = (const float*)d_in[6];
    const float* Wo      = (const float*)d_in[7];
    const float* bo      = (const float*)d_in[8];
    float* out = (float*)d_out;

    cudaFuncSetAttribute(proj_kernel,  cudaFuncAttributeMaxDynamicSharedMemorySize, SMEM_BYTES);
    cudaFuncSetAttribute(score_kernel, cudaFuncAttributeMaxDynamicSharedMemorySize, SMEM_BYTES);
    cudaFuncSetAttribute(pv_kernel,    cudaFuncAttributeMaxDynamicSharedMemorySize, SMEM_BYTES);
    cudaFuncSetAttribute(out_kernel,   cudaFuncAttributeMaxDynamicSharedMemorySize, SMEM_BYTES);

    rope_tab_kernel<<<LL, 64>>>();
    proj_kernel<<<dim3(256, 3), 256, SMEM_BYTES>>>(queries, keys, values, Wq, Wk, Wv);
    score_kernel<<<dim3(8, 8, 32), 256, SMEM_BYTES>>>(mask);
    softmax_kernel<<<NB*HH*LL/8, 256>>>();
    pv_kernel<<<dim3(8, 32), 256, SMEM_BYTES>>>();
    out_kernel<<<dim3(16, 16), 256, SMEM_BYTES>>>(Wo, bo, out);
}